// round 1
// baseline (speedup 1.0000x reference)
#include <cuda_runtime.h>
#include <cuda_bf16.h>

// Problem constants (fixed by the reference).
#define IN_DIM   4096
#define OUT_DIM  4096
#define RANK     16
#define M_TOTAL  8192   // BATCH(4) * SEQ(2048)

// 64 MB scratch for the merged weight W' = W + (w1a@w1b) .* (w2a@w2b) * scalar
__device__ float g_Wm[(size_t)OUT_DIM * IN_DIM];

// ---------------------------------------------------------------------------
// Kernel 1: merge weights.
// Tile: 16 output-rows x 256 input-cols per block. w1b/w2b tiles are staged in
// smem and reused across the 16 o-rows (cuts L2 traffic 16x).
// ---------------------------------------------------------------------------
__global__ __launch_bounds__(256)
void merge_weights_kernel(const float* __restrict__ W,
                          const float* __restrict__ w1a,
                          const float* __restrict__ w1b,
                          const float* __restrict__ w2a,
                          const float* __restrict__ w2b,
                          const float* __restrict__ scalar_p)
{
    __shared__ float a1s[16][RANK];
    __shared__ float a2s[16][RANK];
    __shared__ float b1s[RANK][256];
    __shared__ float b2s[RANK][256];

    const int i0 = blockIdx.x * 256;   // input-col tile
    const int o0 = blockIdx.y * 16;    // output-row tile
    const int t  = threadIdx.x;

    // a tiles: 16 rows x RANK(16) = 256 elements each; one per thread.
    {
        const int oo = t >> 4;   // t / 16
        const int r  = t & 15;   // t % 16
        a1s[oo][r] = w1a[(size_t)(o0 + oo) * RANK + r];
        a2s[oo][r] = w2a[(size_t)(o0 + oo) * RANK + r];
    }
    // b tiles: RANK rows x 256 cols, coalesced.
    #pragma unroll
    for (int r = 0; r < RANK; r++) {
        b1s[r][t] = w1b[(size_t)r * IN_DIM + i0 + t];
        b2s[r][t] = w2b[(size_t)r * IN_DIM + i0 + t];
    }
    __syncthreads();

    const float s = *scalar_p;

    #pragma unroll 4
    for (int oo = 0; oo < 16; oo++) {
        float acc1 = 0.f, acc2 = 0.f;
        #pragma unroll
        for (int r = 0; r < RANK; r++) {
            acc1 = fmaf(a1s[oo][r], b1s[r][t], acc1);
            acc2 = fmaf(a2s[oo][r], b2s[r][t], acc2);
        }
        const size_t idx = (size_t)(o0 + oo) * IN_DIM + i0 + t;
        g_Wm[idx] = W[idx] + acc1 * acc2 * s;
    }
}

// ---------------------------------------------------------------------------
// Kernel 2: y = x @ W'^T + bias
// A = x   [M=8192, K=4096] row-major (K contiguous)
// B = W'  [N=4096, K=4096] row-major (K contiguous)  -> NT GEMM
// Classic 128x128x16 tiling, 256 threads, 8x8 per-thread register block.
// ---------------------------------------------------------------------------
__global__ __launch_bounds__(256, 2)
void gemm_bias_kernel(const float* __restrict__ A,
                      const float* __restrict__ bias,
                      float* __restrict__ C)
{
    constexpr int K  = IN_DIM;
    constexpr int N  = OUT_DIM;
    constexpr int BM = 128, BN = 128, BK = 16;
    constexpr int PAD = 4;

    __shared__ float As[BK][BM + PAD];
    __shared__ float Bs[BK][BN + PAD];

    const float* __restrict__ B = g_Wm;

    const int tid = threadIdx.x;
    const int m0  = blockIdx.y * BM;
    const int n0  = blockIdx.x * BN;

    // Global->smem load mapping: 4 float4 per 16-float row segment.
    const int lr = tid >> 2;          // 0..63 (row within tile, +64 second pass)
    const int lc = (tid & 3) * 4;     // 0,4,8,12 (k offset)

    // Compute mapping: 16x16 thread grid, 8x8 outputs each.
    const int tr = (tid >> 4) * 8;    // row offset in tile
    const int tc = (tid & 15) * 8;    // col offset in tile

    float acc[8][8];
    #pragma unroll
    for (int i = 0; i < 8; i++)
        #pragma unroll
        for (int j = 0; j < 8; j++)
            acc[i][j] = 0.f;

    for (int k0 = 0; k0 < K; k0 += BK) {
        // Load A-tile and B-tile (each 128x16), store transposed [k][m].
        #pragma unroll
        for (int s = 0; s < 2; s++) {
            const int row = lr + s * 64;
            const float4 va = *(const float4*)&A[(size_t)(m0 + row) * K + k0 + lc];
            As[lc + 0][row] = va.x;
            As[lc + 1][row] = va.y;
            As[lc + 2][row] = va.z;
            As[lc + 3][row] = va.w;
            const float4 vb = *(const float4*)&B[(size_t)(n0 + row) * K + k0 + lc];
            Bs[lc + 0][row] = vb.x;
            Bs[lc + 1][row] = vb.y;
            Bs[lc + 2][row] = vb.z;
            Bs[lc + 3][row] = vb.w;
        }
        __syncthreads();

        #pragma unroll
        for (int k = 0; k < BK; k++) {
            float ra[8], rb[8];
            #pragma unroll
            for (int i = 0; i < 8; i += 4) {
                const float4 v = *(const float4*)&As[k][tr + i];
                ra[i] = v.x; ra[i+1] = v.y; ra[i+2] = v.z; ra[i+3] = v.w;
            }
            #pragma unroll
            for (int j = 0; j < 8; j += 4) {
                const float4 v = *(const float4*)&Bs[k][tc + j];
                rb[j] = v.x; rb[j+1] = v.y; rb[j+2] = v.z; rb[j+3] = v.w;
            }
            #pragma unroll
            for (int i = 0; i < 8; i++)
                #pragma unroll
                for (int j = 0; j < 8; j++)
                    acc[i][j] = fmaf(ra[i], rb[j], acc[i][j]);
        }
        __syncthreads();
    }

    // Epilogue: add bias, write out with float4.
    #pragma unroll
    for (int i = 0; i < 8; i++) {
        const int m = m0 + tr + i;
        #pragma unroll
        for (int j = 0; j < 8; j += 4) {
            const int n = n0 + tc + j;
            float4 v;
            v.x = acc[i][j + 0] + bias[n + 0];
            v.y = acc[i][j + 1] + bias[n + 1];
            v.z = acc[i][j + 2] + bias[n + 2];
            v.w = acc[i][j + 3] + bias[n + 3];
            *(float4*)&C[(size_t)m * N + n] = v;
        }
    }
}

// ---------------------------------------------------------------------------
// Launch
// ---------------------------------------------------------------------------
extern "C" void kernel_launch(void* const* d_in, const int* in_sizes, int n_in,
                              void* d_out, int out_size)
{
    const float* x       = (const float*)d_in[0];  // [4,2048,4096]
    const float* org_w   = (const float*)d_in[1];  // [4096,4096]
    const float* org_b   = (const float*)d_in[2];  // [4096]
    const float* w1a     = (const float*)d_in[3];  // [4096,16]
    const float* w1b     = (const float*)d_in[4];  // [16,4096]
    const float* w2a     = (const float*)d_in[5];  // [4096,16]
    const float* w2b     = (const float*)d_in[6];  // [16,4096]
    const float* scalar  = (const float*)d_in[7];  // [1]
    float*       out     = (float*)d_out;          // [4,2048,4096]

    (void)in_sizes; (void)n_in; (void)out_size;

    // 1) W' = W + (w1a@w1b) .* (w2a@w2b) * scalar
    {
        dim3 grid(IN_DIM / 256, OUT_DIM / 16);
        merge_weights_kernel<<<grid, 256>>>(org_w, w1a, w1b, w2a, w2b, scalar);
    }

    // 2) y = x @ W'^T + bias
    {
        dim3 grid(OUT_DIM / 128, M_TOTAL / 128);
        gemm_bias_kernel<<<grid, 256>>>(x, org_b, out);
    }
}

// round 3
// speedup vs baseline: 3.5976x; 3.5976x over previous
#include <cuda_runtime.h>
#include <cuda_fp16.h>
#include <cstdint>

// ---------------------------------------------------------------------------
// Problem constants
// ---------------------------------------------------------------------------
#define IN_DIM   4096
#define OUT_DIM  4096
#define RANK     16
#define M_TOTAL  8192                 // BATCH(4) * SEQ(2048)

// GEMM tiling
#define BM 128
#define BN 256
#define BK 64                         // fp16 per chunk (128 bytes per row)
#define NCH 128                       // virtual K = 8192 (W' hi then lo)
#define STAGES 3

#define A_ST_BYTES (BM * 128)         // 16 KB
#define B_ST_BYTES (BN * 128)         // 32 KB
#define ST_BYTES   (A_ST_BYTES + B_ST_BYTES)          // 48 KB
#define SMEM_TOTAL (STAGES * ST_BYTES)                // 144 KB

#define N_MTILES (M_TOTAL / BM)       // 64
#define N_NTILES (OUT_DIM / BN)       // 16

// Packed fp16 operands in global scratch.
// g_A: x * 0.125 as fp16, [M][K]
// g_B: merged weight * 8, split hi/lo fp16: [2][N][K]
__device__ __align__(128) __half g_A[(size_t)M_TOTAL * IN_DIM];
__device__ __align__(128) __half g_B[2][(size_t)OUT_DIM * IN_DIM];

// ---------------------------------------------------------------------------
// Helpers
// ---------------------------------------------------------------------------
__device__ __forceinline__ uint32_t smem_u32(const void* p) {
    uint32_t a;
    asm("{ .reg .u64 t; cvta.to.shared.u64 t, %1; cvt.u32.u64 %0, t; }" : "=r"(a) : "l"(p));
    return a;
}

__device__ __forceinline__ uint32_t swz128(uint32_t off) {
    return off ^ ((off >> 3) & 0x70);
}

__device__ __forceinline__ void cp16(uint32_t dst, const void* src) {
    asm volatile("cp.async.cg.shared.global [%0], [%1], 16;" :: "r"(dst), "l"(src));
}
#define CP_COMMIT() asm volatile("cp.async.commit_group;" ::: "memory")
#define CP_WAIT1()  asm volatile("cp.async.wait_group 1;" ::: "memory")

#define LDSM4(r0, r1, r2, r3, addr) \
    asm volatile("ldmatrix.sync.aligned.m8n8.x4.shared.b16 {%0,%1,%2,%3}, [%4];" \
                 : "=r"(r0), "=r"(r1), "=r"(r2), "=r"(r3) : "r"(addr))

__device__ __forceinline__ void mma16816(float* d, const uint32_t* a,
                                         uint32_t b0, uint32_t b1) {
    asm volatile(
        "mma.sync.aligned.m16n8k16.row.col.f32.f16.f16.f32 "
        "{%0,%1,%2,%3}, {%4,%5,%6,%7}, {%8,%9}, {%0,%1,%2,%3};"
        : "+f"(d[0]), "+f"(d[1]), "+f"(d[2]), "+f"(d[3])
        : "r"(a[0]), "r"(a[1]), "r"(a[2]), "r"(a[3]), "r"(b0), "r"(b1));
}

// ---------------------------------------------------------------------------
// Pack x -> fp16 (scaled by 1/8): g_A[m][k] = f16(x * 0.125)
// ---------------------------------------------------------------------------
__global__ __launch_bounds__(256)
void pack_x_kernel(const float* __restrict__ x)
{
    const size_t idx = ((size_t)blockIdx.x * 256 + threadIdx.x) * 4;
    const float4 v = *(const float4*)&x[idx];
    __half2 p0 = __floats2half2_rn(v.x * 0.125f, v.y * 0.125f);
    __half2 p1 = __floats2half2_rn(v.z * 0.125f, v.w * 0.125f);
    *(uint2*)&g_A[idx] = make_uint2(*(uint32_t*)&p0, *(uint32_t*)&p1);
}

// ---------------------------------------------------------------------------
// Merge weights, scale by 8, split into fp16 hi/lo.
// Tile: 16 output-rows x 256 input-cols per block (b-tiles staged in smem).
// ---------------------------------------------------------------------------
__global__ __launch_bounds__(256)
void pack_w_kernel(const float* __restrict__ W,
                   const float* __restrict__ w1a, const float* __restrict__ w1b,
                   const float* __restrict__ w2a, const float* __restrict__ w2b,
                   const float* __restrict__ scalar_p)
{
    __shared__ float a1s[16][RANK];
    __shared__ float a2s[16][RANK];
    __shared__ float b1s[RANK][256];
    __shared__ float b2s[RANK][256];

    const int i0 = blockIdx.x * 256;
    const int o0 = blockIdx.y * 16;
    const int t  = threadIdx.x;

    {
        const int oo = t >> 4;
        const int r  = t & 15;
        a1s[oo][r] = w1a[(size_t)(o0 + oo) * RANK + r];
        a2s[oo][r] = w2a[(size_t)(o0 + oo) * RANK + r];
    }
    #pragma unroll
    for (int r = 0; r < RANK; r++) {
        b1s[r][t] = w1b[(size_t)r * IN_DIM + i0 + t];
        b2s[r][t] = w2b[(size_t)r * IN_DIM + i0 + t];
    }
    __syncthreads();

    const float s = *scalar_p;

    #pragma unroll 4
    for (int oo = 0; oo < 16; oo++) {
        float acc1 = 0.f, acc2 = 0.f;
        #pragma unroll
        for (int r = 0; r < RANK; r++) {
            acc1 = fmaf(a1s[oo][r], b1s[r][t], acc1);
            acc2 = fmaf(a2s[oo][r], b2s[r][t], acc2);
        }
        const size_t idx = (size_t)(o0 + oo) * IN_DIM + i0 + t;
        const float v8 = (W[idx] + acc1 * acc2 * s) * 8.0f;
        const __half h = __float2half_rn(v8);
        const __half l = __float2half_rn(v8 - __half2float(h));
        g_B[0][idx] = h;
        g_B[1][idx] = l;
    }
}

// ---------------------------------------------------------------------------
// Main GEMM: C[m][n] = sum over virtual K=8192 of A[m][k]*Bsel[n][k] + bias[n]
// 256 threads, 8 warps (2x4 grid of 64x64 warp tiles), 3-stage cp.async pipe.
// ---------------------------------------------------------------------------
__global__ __launch_bounds__(256, 1)
void hgemm_kernel(const float* __restrict__ bias, float* __restrict__ C)
{
    extern __shared__ char smem[];
    const uint32_t sb = smem_u32(smem);

    const int t    = threadIdx.x;
    const int wid  = t >> 5;
    const int lane = t & 31;
    const int nt   = blockIdx.x;       // 0..15
    const int mt   = blockIdx.y;       // 0..63

    // global load mapping: seg s = t + i*256; row = s>>3, col16 = s&7
    const int r0 = t >> 3;             // 0..31
    const int c0 = t & 7;              // 0..7

    const __half* Abase = g_A + (size_t)(mt * BM) * IN_DIM;

    // producer for chunk c into stage st
    auto issue = [&](int c, int st) {
        const int sel = c >> 6;
        const int k0  = (c & 63) * BK;
        const uint32_t aB = sb + st * ST_BYTES;
        const uint32_t bB = aB + A_ST_BYTES;
        const __half* As = Abase + k0;
        const __half* Bs = g_B[sel] + (size_t)(nt * BN) * IN_DIM + k0;
        #pragma unroll
        for (int i = 0; i < 4; i++) {
            const int row = r0 + i * 32;
            cp16(aB + swz128((uint32_t)(row * 128 + c0 * 16)),
                 As + (size_t)row * IN_DIM + c0 * 8);
        }
        #pragma unroll
        for (int i = 0; i < 8; i++) {
            const int row = r0 + i * 32;
            cp16(bB + swz128((uint32_t)(row * 128 + c0 * 16)),
                 Bs + (size_t)row * IN_DIM + c0 * 8);
        }
        CP_COMMIT();
    };

    // prologue: stages 0,1
    issue(0, 0);
    issue(1, 1);

    // compute-side per-thread constants
    const int wr = (wid >> 2) * 64;     // warp m offset
    const int wc = (wid & 3) * 64;      // warp n offset
    const int l15 = lane & 15;
    const int l16 = lane >> 4;
    const uint32_t aoff0 = (uint32_t)((wr + l15) * 128 + l16 * 16);
    const uint32_t boff0 = (uint32_t)((wc + l15) * 128 + l16 * 16);

    float acc[4][8][4];
    #pragma unroll
    for (int i = 0; i < 4; i++)
        #pragma unroll
        for (int j = 0; j < 8; j++)
            #pragma unroll
            for (int q = 0; q < 4; q++)
                acc[i][j][q] = 0.f;

    for (int c = 0; c < NCH; c++) {
        CP_WAIT1();
        __syncthreads();

        if (c + 2 < NCH) issue(c + 2, (c + 2) % STAGES);
        else             CP_COMMIT();   // keep group bookkeeping uniform

        const uint32_t aB = sb + (c % STAGES) * ST_BYTES;
        const uint32_t bB = aB + A_ST_BYTES;

        #pragma unroll
        for (int ks = 0; ks < 4; ks++) {
            const uint32_t kadd = ks * 32;
            uint32_t a[4][4];
            #pragma unroll
            for (int mf = 0; mf < 4; mf++)
                LDSM4(a[mf][0], a[mf][1], a[mf][2], a[mf][3],
                      aB + swz128(aoff0 + mf * 2048 + kadd));
            uint32_t b[4][4];
            #pragma unroll
            for (int nf = 0; nf < 4; nf++)
                LDSM4(b[nf][0], b[nf][1], b[nf][2], b[nf][3],
                      bB + swz128(boff0 + nf * 2048 + kadd));
            #pragma unroll
            for (int mf = 0; mf < 4; mf++)
                #pragma unroll
                for (int nf = 0; nf < 4; nf++) {
                    mma16816(acc[mf][2 * nf],     a[mf], b[nf][0], b[nf][2]);
                    mma16816(acc[mf][2 * nf + 1], a[mf], b[nf][1], b[nf][3]);
                }
        }
    }

    // epilogue
    const int l4 = lane >> 2;
    const int l3 = lane & 3;
    #pragma unroll
    for (int mf = 0; mf < 4; mf++) {
        const int mrow = mt * BM + wr + mf * 16 + l4;
        #pragma unroll
        for (int nf = 0; nf < 8; nf++) {
            const int n = nt * BN + wc + nf * 8 + l3 * 2;
            const float2 bv = *(const float2*)&bias[n];
            float2 o0, o1;
            o0.x = acc[mf][nf][0] + bv.x;
            o0.y = acc[mf][nf][1] + bv.y;
            o1.x = acc[mf][nf][2] + bv.x;
            o1.y = acc[mf][nf][3] + bv.y;
            *(float2*)&C[(size_t)mrow * OUT_DIM + n] = o0;
            *(float2*)&C[(size_t)(mrow + 8) * OUT_DIM + n] = o1;
        }
    }
}

// ---------------------------------------------------------------------------
// Launch
// ---------------------------------------------------------------------------
extern "C" void kernel_launch(void* const* d_in, const int* in_sizes, int n_in,
                              void* d_out, int out_size)
{
    const float* x      = (const float*)d_in[0];
    const float* org_w  = (const float*)d_in[1];
    const float* org_b  = (const float*)d_in[2];
    const float* w1a    = (const float*)d_in[3];
    const float* w1b    = (const float*)d_in[4];
    const float* w2a    = (const float*)d_in[5];
    const float* w2b    = (const float*)d_in[6];
    const float* scalar = (const float*)d_in[7];
    float*       out    = (float*)d_out;
    (void)in_sizes; (void)n_in; (void)out_size;

    static bool attr_set = false;
    if (!attr_set) {
        cudaFuncSetAttribute(hgemm_kernel,
                             cudaFuncAttributeMaxDynamicSharedMemorySize, SMEM_TOTAL);
        attr_set = true;
    }

    pack_x_kernel<<<(M_TOTAL * (size_t)IN_DIM) / (256 * 4), 256>>>(x);
    pack_w_kernel<<<dim3(IN_DIM / 256, OUT_DIM / 16), 256>>>(org_w, w1a, w1b, w2a, w2b, scalar);
    hgemm_kernel<<<dim3(N_NTILES, N_MTILES), 256, SMEM_TOTAL>>>(org_b, out);
}

// round 4
// speedup vs baseline: 6.7751x; 1.8832x over previous
#include <cuda_runtime.h>
#include <cuda_fp16.h>
#include <cstdint>

// ---------------------------------------------------------------------------
// Problem constants
// ---------------------------------------------------------------------------
#define IN_DIM   4096
#define OUT_DIM  4096
#define RANK     16
#define M_TOTAL  8192                 // BATCH(4) * SEQ(2048)

// GEMM tiling
#define BM 128
#define BN 256
#define BK 64                         // fp16 per chunk (128 bytes per row)
#define NCH (IN_DIM / BK)             // 64 (single fp16 pass, K = 4096)
#define STAGES 4

#define A_ST_BYTES (BM * 128)         // 16 KB
#define B_ST_BYTES (BN * 128)         // 32 KB
#define ST_BYTES   (A_ST_BYTES + B_ST_BYTES)          // 48 KB
#define SMEM_TOTAL (STAGES * ST_BYTES)                // 192 KB

#define N_MTILES (M_TOTAL / BM)       // 64
#define N_NTILES (OUT_DIM / BN)       // 16

// Packed fp16 operands in global scratch.
__device__ __align__(128) __half g_A[(size_t)M_TOTAL * IN_DIM];
__device__ __align__(128) __half g_B[(size_t)OUT_DIM * IN_DIM];

// ---------------------------------------------------------------------------
// Helpers
// ---------------------------------------------------------------------------
__device__ __forceinline__ uint32_t smem_u32(const void* p) {
    uint32_t a;
    asm("{ .reg .u64 t; cvta.to.shared.u64 t, %1; cvt.u32.u64 %0, t; }" : "=r"(a) : "l"(p));
    return a;
}

__device__ __forceinline__ uint32_t swz128(uint32_t off) {
    return off ^ ((off >> 3) & 0x70);
}

__device__ __forceinline__ void cp16(uint32_t dst, const void* src) {
    asm volatile("cp.async.cg.shared.global [%0], [%1], 16;" :: "r"(dst), "l"(src));
}
#define CP_COMMIT() asm volatile("cp.async.commit_group;" ::: "memory")
#define CP_WAIT2()  asm volatile("cp.async.wait_group 2;" ::: "memory")

#define LDSM4(r0, r1, r2, r3, addr) \
    asm volatile("ldmatrix.sync.aligned.m8n8.x4.shared.b16 {%0,%1,%2,%3}, [%4];" \
                 : "=r"(r0), "=r"(r1), "=r"(r2), "=r"(r3) : "r"(addr))

__device__ __forceinline__ void mma16816(float* d, const uint32_t* a,
                                         uint32_t b0, uint32_t b1) {
    asm volatile(
        "mma.sync.aligned.m16n8k16.row.col.f32.f16.f16.f32 "
        "{%0,%1,%2,%3}, {%4,%5,%6,%7}, {%8,%9}, {%0,%1,%2,%3};"
        : "+f"(d[0]), "+f"(d[1]), "+f"(d[2]), "+f"(d[3])
        : "r"(a[0]), "r"(a[1]), "r"(a[2]), "r"(a[3]), "r"(b0), "r"(b1));
}

// ---------------------------------------------------------------------------
// Pack x -> fp16
// ---------------------------------------------------------------------------
__global__ __launch_bounds__(256)
void pack_x_kernel(const float* __restrict__ x)
{
    const size_t idx = ((size_t)blockIdx.x * 256 + threadIdx.x) * 4;
    const float4 v = *(const float4*)&x[idx];
    __half2 p0 = __floats2half2_rn(v.x, v.y);
    __half2 p1 = __floats2half2_rn(v.z, v.w);
    *(uint2*)&g_A[idx] = make_uint2(*(uint32_t*)&p0, *(uint32_t*)&p1);
}

// ---------------------------------------------------------------------------
// Merge weights -> fp16: g_B = f16(W + (w1a@w1b).*(w2a@w2b)*scalar)
// ---------------------------------------------------------------------------
__global__ __launch_bounds__(256)
void pack_w_kernel(const float* __restrict__ W,
                   const float* __restrict__ w1a, const float* __restrict__ w1b,
                   const float* __restrict__ w2a, const float* __restrict__ w2b,
                   const float* __restrict__ scalar_p)
{
    __shared__ float a1s[16][RANK];
    __shared__ float a2s[16][RANK];
    __shared__ float b1s[RANK][256];
    __shared__ float b2s[RANK][256];

    const int i0 = blockIdx.x * 256;
    const int o0 = blockIdx.y * 16;
    const int t  = threadIdx.x;

    {
        const int oo = t >> 4;
        const int r  = t & 15;
        a1s[oo][r] = w1a[(size_t)(o0 + oo) * RANK + r];
        a2s[oo][r] = w2a[(size_t)(o0 + oo) * RANK + r];
    }
    #pragma unroll
    for (int r = 0; r < RANK; r++) {
        b1s[r][t] = w1b[(size_t)r * IN_DIM + i0 + t];
        b2s[r][t] = w2b[(size_t)r * IN_DIM + i0 + t];
    }
    __syncthreads();

    const float s = *scalar_p;

    #pragma unroll 4
    for (int oo = 0; oo < 16; oo++) {
        float acc1 = 0.f, acc2 = 0.f;
        #pragma unroll
        for (int r = 0; r < RANK; r++) {
            acc1 = fmaf(a1s[oo][r], b1s[r][t], acc1);
            acc2 = fmaf(a2s[oo][r], b2s[r][t], acc2);
        }
        const size_t idx = (size_t)(o0 + oo) * IN_DIM + i0 + t;
        g_B[idx] = __float2half_rn(W[idx] + acc1 * acc2 * s);
    }
}

// ---------------------------------------------------------------------------
// Main GEMM: C[m][n] = sum_k A[m][k]*B[n][k] + bias[n]
// 256 threads, 8 warps (2x4 grid of 64x64 warp tiles), 4-stage cp.async pipe.
// ---------------------------------------------------------------------------
__global__ __launch_bounds__(256, 1)
void hgemm_kernel(const float* __restrict__ bias, float* __restrict__ C)
{
    extern __shared__ char smem[];
    const uint32_t sb = smem_u32(smem);

    const int t    = threadIdx.x;
    const int wid  = t >> 5;
    const int lane = t & 31;
    const int nt   = blockIdx.x;       // 0..15
    const int mt   = blockIdx.y;       // 0..63

    const int r0 = t >> 3;             // 0..31
    const int c0 = t & 7;              // 0..7

    const __half* Abase = g_A + (size_t)(mt * BM) * IN_DIM;
    const __half* Bbase = g_B + (size_t)(nt * BN) * IN_DIM;

    auto issue = [&](int c, int st) {
        const int k0 = c * BK;
        const uint32_t aB = sb + st * ST_BYTES;
        const uint32_t bB = aB + A_ST_BYTES;
        const __half* As = Abase + k0;
        const __half* Bs = Bbase + k0;
        #pragma unroll
        for (int i = 0; i < 4; i++) {
            const int row = r0 + i * 32;
            cp16(aB + swz128((uint32_t)(row * 128 + c0 * 16)),
                 As + (size_t)row * IN_DIM + c0 * 8);
        }
        #pragma unroll
        for (int i = 0; i < 8; i++) {
            const int row = r0 + i * 32;
            cp16(bB + swz128((uint32_t)(row * 128 + c0 * 16)),
                 Bs + (size_t)row * IN_DIM + c0 * 8);
        }
        CP_COMMIT();
    };

    // prologue: 3 stages in flight
    issue(0, 0);
    issue(1, 1);
    issue(2, 2);

    const int wr = (wid >> 2) * 64;     // warp m offset
    const int wc = (wid & 3) * 64;      // warp n offset
    const int l15 = lane & 15;
    const int l16 = lane >> 4;
    const uint32_t aoff0 = (uint32_t)((wr + l15) * 128 + l16 * 16);
    const uint32_t boff0 = (uint32_t)((wc + l15) * 128 + l16 * 16);

    float acc[4][8][4];
    #pragma unroll
    for (int i = 0; i < 4; i++)
        #pragma unroll
        for (int j = 0; j < 8; j++)
            #pragma unroll
            for (int q = 0; q < 4; q++)
                acc[i][j][q] = 0.f;

    for (int c = 0; c < NCH; c++) {
        CP_WAIT2();
        __syncthreads();

        if (c + 3 < NCH) issue(c + 3, (c + 3) % STAGES);
        else             CP_COMMIT();   // dummy group: keep wait depth uniform

        const uint32_t aB = sb + (c % STAGES) * ST_BYTES;
        const uint32_t bB = aB + A_ST_BYTES;

        #pragma unroll
        for (int ks = 0; ks < 4; ks++) {
            const uint32_t kadd = ks * 32;
            uint32_t a[4][4];
            #pragma unroll
            for (int mf = 0; mf < 4; mf++)
                LDSM4(a[mf][0], a[mf][1], a[mf][2], a[mf][3],
                      aB + swz128(aoff0 + mf * 2048 + kadd));
            uint32_t b[4][4];
            #pragma unroll
            for (int nf = 0; nf < 4; nf++)
                LDSM4(b[nf][0], b[nf][1], b[nf][2], b[nf][3],
                      bB + swz128(boff0 + nf * 2048 + kadd));
            #pragma unroll
            for (int mf = 0; mf < 4; mf++)
                #pragma unroll
                for (int nf = 0; nf < 4; nf++) {
                    mma16816(acc[mf][2 * nf],     a[mf], b[nf][0], b[nf][2]);
                    mma16816(acc[mf][2 * nf + 1], a[mf], b[nf][1], b[nf][3]);
                }
        }
    }

    // epilogue
    const int l4 = lane >> 2;
    const int l3 = lane & 3;
    #pragma unroll
    for (int mf = 0; mf < 4; mf++) {
        const int mrow = mt * BM + wr + mf * 16 + l4;
        #pragma unroll
        for (int nf = 0; nf < 8; nf++) {
            const int n = nt * BN + wc + nf * 8 + l3 * 2;
            const float2 bv = *(const float2*)&bias[n];
            float2 o0, o1;
            o0.x = acc[mf][nf][0] + bv.x;
            o0.y = acc[mf][nf][1] + bv.y;
            o1.x = acc[mf][nf][2] + bv.x;
            o1.y = acc[mf][nf][3] + bv.y;
            *(float2*)&C[(size_t)mrow * OUT_DIM + n] = o0;
            *(float2*)&C[(size_t)(mrow + 8) * OUT_DIM + n] = o1;
        }
    }
}

// ---------------------------------------------------------------------------
// Launch
// ---------------------------------------------------------------------------
extern "C" void kernel_launch(void* const* d_in, const int* in_sizes, int n_in,
                              void* d_out, int out_size)
{
    const float* x      = (const float*)d_in[0];
    const float* org_w  = (const float*)d_in[1];
    const float* org_b  = (const float*)d_in[2];
    const float* w1a    = (const float*)d_in[3];
    const float* w1b    = (const float*)d_in[4];
    const float* w2a    = (const float*)d_in[5];
    const float* w2b    = (const float*)d_in[6];
    const float* scalar = (const float*)d_in[7];
    float*       out    = (float*)d_out;
    (void)in_sizes; (void)n_in; (void)out_size;

    static bool attr_set = false;
    if (!attr_set) {
        cudaFuncSetAttribute(hgemm_kernel,
                             cudaFuncAttributeMaxDynamicSharedMemorySize, SMEM_TOTAL);
        attr_set = true;
    }

    pack_x_kernel<<<(M_TOTAL * (size_t)IN_DIM) / (256 * 4), 256>>>(x);
    pack_w_kernel<<<dim3(IN_DIM / 256, OUT_DIM / 16), 256>>>(org_w, w1a, w1b, w2a, w2b, scalar);
    hgemm_kernel<<<dim3(N_NTILES, N_MTILES), 256, SMEM_TOTAL>>>(org_b, out);
}